// round 5
// baseline (speedup 1.0000x reference)
#include <cuda_runtime.h>
#include <stdint.h>

#define NTOK 16384
#define DDIM 512
#define HDIM 2048
#define NEXP 8
#define NPAIR (NTOK * 2)

// ---------------- device scratch (allocation-free) ----------------
__device__ int g_count[NEXP];
__device__ int g_base[NEXP];
__device__ int g_i64;
__device__ int g_list[NEXP * NTOK];            // entries: token*2 + slot
__device__ unsigned char g_v1[NTOK];
__device__ float g_xc[(size_t)NTOK * DDIM];    // tf32-rounded x
__device__ float g_W1t[(size_t)NEXP * DDIM * HDIM];  // [E][H][D] K-major
__device__ float g_W2t[(size_t)NEXP * DDIM * HDIM];  // [E][D][H] K-major
__device__ float g_h[((size_t)NPAIR + 128) * HDIM];  // compacted hidden
__device__ float g_y[(size_t)NPAIR * DDIM];

// ---------------- helpers ----------------
__device__ __forceinline__ uint32_t smem_to_u32(const void* p) {
    uint32_t a;
    asm("{ .reg .u64 t; cvta.to.shared.u64 t, %1; cvt.u32.u64 %0, t; }"
        : "=r"(a) : "l"(p));
    return a;
}
__device__ __forceinline__ float totf32(float f) {
    uint32_t u;
    asm("cvt.rna.tf32.f32 %0, %1;" : "=r"(u) : "f"(f));
    return __uint_as_float(u);
}
#define CP_ASYNC16(saddr, gptr) \
    asm volatile("cp.async.cg.shared.global [%0], [%1], 16;" :: "r"(saddr), "l"(gptr))
#define CP_COMMIT() asm volatile("cp.async.commit_group;" ::: "memory")
#define CP_WAIT2() asm volatile("cp.async.wait_group 2;" ::: "memory")

__device__ __forceinline__ void mma_tf32(float* c, const uint32_t* a, const uint32_t* b) {
    asm volatile(
        "mma.sync.aligned.m16n8k8.row.col.f32.tf32.tf32.f32 "
        "{%0,%1,%2,%3}, {%4,%5,%6,%7}, {%8,%9}, {%0,%1,%2,%3};"
        : "+f"(c[0]), "+f"(c[1]), "+f"(c[2]), "+f"(c[3])
        : "r"(a[0]), "r"(a[1]), "r"(a[2]), "r"(a[3]), "r"(b[0]), "r"(b[1]));
}
#define LDSM_X4(r0, r1, r2, r3, addr) \
    asm volatile("ldmatrix.sync.aligned.x4.m8n8.shared.b16 {%0,%1,%2,%3}, [%4];" \
                 : "=r"(r0), "=r"(r1), "=r"(r2), "=r"(r3) : "r"(addr))

// ---------------- routing ----------------
__global__ void prep_kernel(const int* __restrict__ aw) {
    __shared__ int nz;
    if (threadIdx.x == 0) nz = 0;
    __syncthreads();
    if (threadIdx.x < 64)
        if (aw[2 * threadIdx.x + 1] != 0) atomicOr(&nz, 1);
    __syncthreads();
    if (threadIdx.x < NEXP) g_count[threadIdx.x] = 0;
    if (threadIdx.x == 0) g_i64 = (nz == 0) ? 1 : 0;
}

__global__ void route_kernel(const int* __restrict__ aw) {
    int t = blockIdx.x * blockDim.x + threadIdx.x;
    if (t >= NTOK) return;
    int e0, e1;
    if (g_i64) { e0 = aw[4 * t]; e1 = aw[4 * t + 2]; }
    else       { e0 = aw[2 * t]; e1 = aw[2 * t + 1]; }
    int p = atomicAdd(&g_count[e0], 1);
    g_list[e0 * NTOK + p] = 2 * t;
    int v1 = (e1 != e0) ? 1 : 0;
    g_v1[t] = (unsigned char)v1;
    if (v1) {
        p = atomicAdd(&g_count[e1], 1);
        g_list[e1 * NTOK + p] = 2 * t + 1;
    }
}

__global__ void base_kernel() {
    if (threadIdx.x == 0) {
        int s = 0;
        for (int e = 0; e < NEXP; e++) { g_base[e] = s; s += g_count[e]; }
    }
}

// ---------------- input rounding / weight transpose ----------------
__global__ void xconv_kernel(const float* __restrict__ x) {
    size_t i = (size_t)blockIdx.x * blockDim.x + threadIdx.x;
    float4 v = ((const float4*)x)[i];
    v.x = totf32(v.x); v.y = totf32(v.y); v.z = totf32(v.z); v.w = totf32(v.w);
    ((float4*)g_xc)[i] = v;
}

// in: [E][R][C] -> out: [E][C][R], tf32-rounded
__global__ void transpose_kernel(const float* __restrict__ in, int R, int C, int which) {
    __shared__ float t[32][33];
    float* out = which ? g_W2t : g_W1t;
    int e = blockIdx.z;
    const float* I = in + (size_t)e * R * C;
    float* O = out + (size_t)e * R * C;
    int c0 = blockIdx.x * 32, r0 = blockIdx.y * 32;
    int tx = threadIdx.x, ty = threadIdx.y;
#pragma unroll
    for (int j = 0; j < 32; j += 8)
        t[ty + j][tx] = totf32(I[(size_t)(r0 + ty + j) * C + c0 + tx]);
    __syncthreads();
#pragma unroll
    for (int j = 0; j < 32; j += 8)
        O[(size_t)(c0 + ty + j) * R + r0 + tx] = t[tx][ty + j];
}

// ---------------- tf32 mma.sync gather-GEMM ----------------
// CTA tile 128(M) x 256(N), BK=32, 512 threads (warps 2M x 8N, warp tile 64x32).
// 4-stage cp.async ring, ONE __syncthreads per K-stage.
// smem rows padded: stride 36 floats (144B) -> conflict-free LDSM.
#define ASTRIDE 36
#define ABUF (128 * ASTRIDE)
#define BBUF (256 * ASTRIDE)
#define ABYTES (ABUF * 4)               // 18432
#define BBYTES (BBUF * 4)               // 36864
#define NSTG 4
#define SMEM_BYTES (NSTG * (ABYTES + BBYTES))   // 221184

// MODE 1: h = relu(xc @ W1t^T + b1)  KD=512,  ND=2048, out rows compact
// MODE 2: y = h @ W2t^T + b2         KD=2048, ND=512,  out rows scattered by list
template <int MODE>
__global__ __launch_bounds__(512, 1) void moe_mma(const float* __restrict__ biasAll) {
    constexpr int KD = (MODE == 1) ? DDIM : HDIM;
    constexpr int ND = (MODE == 1) ? HDIM : DDIM;
    constexpr int NS = KD / 32;

    const int e = blockIdx.z;
    const int count = g_count[e];
    const int m0 = blockIdx.y * 128;
    if (m0 >= count) return;
    const int n0 = blockIdx.x * 256;
    const int baseE = g_base[e];
    const float* __restrict__ W = (MODE == 1 ? g_W1t : g_W2t) + (size_t)e * KD * ND;
    const float* __restrict__ bias = biasAll + e * ND;
    const int* __restrict__ list = g_list + e * NTOK;

    extern __shared__ float smf[];
    const uint32_t sbase = smem_to_u32(smf);
    const uint32_t sbbase = sbase + NSTG * ABYTES;

    const int tid = threadIdx.x;
    const int wid = tid >> 5, lid = tid & 31;
    const int wm = wid >> 3, wn = wid & 7;         // warp grid 2(M) x 8(N)
    const int g = lid >> 2, tg = lid & 3;

    // ---- cp.async mapping
    // A: 128 rows x 128B; 4 threads/row, 2x16B chunks each
    const int rA = tid >> 2;
    const int cA = (tid & 3) * 2;      // 16B chunk index (0,2,4,6)
    int gmA = m0 + rA;
    if (gmA >= count) gmA = count - 1;
    const float* asrc;
    if (MODE == 1) asrc = g_xc + (size_t)(list[gmA] >> 1) * DDIM + cA * 4;
    else           asrc = g_h + (size_t)(baseE + gmA) * HDIM + cA * 4;
    const uint32_t aoff = sbase + (uint32_t)(rA * ASTRIDE + cA * 4) * 4;
    // B: 256 rows x 128B; 2 threads/row, 4x16B chunks each
    const int rB = tid >> 1;
    const int cB = (tid & 1) * 4;
    const float* bsrc = W + (size_t)(n0 + rB) * KD + cB * 4;
    const uint32_t boff = sbbase + (uint32_t)(rB * ASTRIDE + cB * 4) * 4;

    // ---- ldmatrix per-thread addresses (byte offsets within a stage buffer)
    uint32_t lma[4];
#pragma unroll
    for (int i = 0; i < 4; i++) {
        int row = wm * 64 + i * 16 + ((lid >> 3) & 1) * 8 + (lid & 7);
        lma[i] = (uint32_t)(row * ASTRIDE + ((lid >> 4) & 1) * 4) * 4;
    }
    uint32_t lmb[2];
#pragma unroll
    for (int p = 0; p < 2; p++) {
        int row = wn * 32 + (p * 2 + ((lid >> 4) & 1)) * 8 + (lid & 7);
        lmb[p] = (uint32_t)(row * ASTRIDE + ((lid >> 3) & 1) * 4) * 4;
    }

    float acc[4][4][4];
#pragma unroll
    for (int i = 0; i < 4; i++)
#pragma unroll
        for (int j = 0; j < 4; j++)
#pragma unroll
            for (int q = 0; q < 4; q++) acc[i][j][q] = 0.f;

    auto load_stage = [&](int s) {
        const int buf = s & (NSTG - 1);
        const int k0 = s * 32;
#pragma unroll
        for (int j = 0; j < 2; j++)
            CP_ASYNC16(aoff + buf * ABYTES + j * 16, asrc + k0 + j * 4);
#pragma unroll
        for (int j = 0; j < 4; j++)
            CP_ASYNC16(boff + buf * BBYTES + j * 16, bsrc + k0 + j * 4);
        CP_COMMIT();
    };

    load_stage(0);
    load_stage(1);
    load_stage(2);

    for (int s = 0; s < NS; s++) {
        CP_WAIT2();          // stage s resident (<=2 groups pending: s+1, s+2)
        __syncthreads();     // all warps done reading stage s-1; its buffer is free
        if (s + 3 < NS) load_stage(s + 3);  // writes buffer (s-1) & 3

        const uint32_t sa = sbase + (uint32_t)(s & (NSTG - 1)) * ABYTES;
        const uint32_t sb = sbbase + (uint32_t)(s & (NSTG - 1)) * BBYTES;
#pragma unroll
        for (int ks = 0; ks < 4; ks++) {
            const uint32_t kb = (uint32_t)ks * 32;
            uint32_t a[4][4], b[2][4];
#pragma unroll
            for (int i = 0; i < 4; i++)
                LDSM_X4(a[i][0], a[i][1], a[i][2], a[i][3], sa + lma[i] + kb);
#pragma unroll
            for (int p = 0; p < 2; p++)
                LDSM_X4(b[p][0], b[p][1], b[p][2], b[p][3], sb + lmb[p] + kb);
#pragma unroll
            for (int i = 0; i < 4; i++)
#pragma unroll
                for (int j = 0; j < 4; j++)
                    mma_tf32(acc[i][j], a[i], &b[j >> 1][(j & 1) * 2]);
        }
    }

    // ---- epilogue: bias (+relu(+tf32 re-round)), scatter per mma row layout
#pragma unroll
    for (int i = 0; i < 4; i++) {
#pragma unroll
        for (int half = 0; half < 2; half++) {
            int gm = m0 + wm * 64 + i * 16 + half * 8 + g;
            if (gm >= count) continue;
            float* orow;
            if (MODE == 1) orow = g_h + (size_t)(baseE + gm) * HDIM + n0;
            else           { int ent = list[gm]; orow = g_y + (size_t)ent * DDIM + n0; }
#pragma unroll
            for (int j = 0; j < 4; j++) {
                int col = wn * 32 + j * 8 + tg * 2;
                float2 bv = *(const float2*)(bias + n0 + col);
                float v0 = acc[i][j][2 * half + 0] + bv.x;
                float v1 = acc[i][j][2 * half + 1] + bv.y;
                if (MODE == 1) {
                    v0 = totf32(fmaxf(v0, 0.f));
                    v1 = totf32(fmaxf(v1, 0.f));
                }
                *(float2*)(orow + col) = make_float2(v0, v1);
            }
        }
    }
}

// ---------------- combine ----------------
__global__ void combine_kernel(float* __restrict__ out) {
    int idx = blockIdx.x * blockDim.x + threadIdx.x;
    if (idx >= NTOK * DDIM / 4) return;
    int t = idx / (DDIM / 4);
    int d4 = idx % (DDIM / 4);
    float4 v = ((const float4*)(g_y + (size_t)(2 * t) * DDIM))[d4];
    if (g_v1[t]) {
        float4 w = ((const float4*)(g_y + (size_t)(2 * t + 1) * DDIM))[d4];
        v.x += w.x; v.y += w.y; v.z += w.z; v.w += w.w;
    }
    v.x *= 0.5f; v.y *= 0.5f; v.z *= 0.5f; v.w *= 0.5f;
    ((float4*)out)[idx] = v;
}

// ---------------- launch ----------------
extern "C" void kernel_launch(void* const* d_in, const int* in_sizes, int n_in,
                              void* d_out, int out_size) {
    const float* x  = (const float*)d_in[0];
    const int*   aw = (const int*)d_in[1];
    const float* W1 = (const float*)d_in[2];
    const float* b1 = (const float*)d_in[3];
    const float* W2 = (const float*)d_in[4];
    const float* b2 = (const float*)d_in[5];
    float* out = (float*)d_out;

    cudaFuncSetAttribute(moe_mma<1>, cudaFuncAttributeMaxDynamicSharedMemorySize, SMEM_BYTES);
    cudaFuncSetAttribute(moe_mma<2>, cudaFuncAttributeMaxDynamicSharedMemorySize, SMEM_BYTES);

    prep_kernel<<<1, 256>>>(aw);
    route_kernel<<<NTOK / 256, 256>>>(aw);
    base_kernel<<<1, 32>>>();
    xconv_kernel<<<(NTOK * DDIM / 4) / 256, 256>>>(x);
    transpose_kernel<<<dim3(HDIM / 32, DDIM / 32, NEXP), dim3(32, 8)>>>(W1, DDIM, HDIM, 0);
    transpose_kernel<<<dim3(DDIM / 32, HDIM / 32, NEXP), dim3(32, 8)>>>(W2, HDIM, DDIM, 1);
    moe_mma<1><<<dim3(HDIM / 256, NTOK / 128, NEXP), 512, SMEM_BYTES>>>(b1);
    moe_mma<2><<<dim3(DDIM / 256, NTOK / 128, NEXP), 512, SMEM_BYTES>>>(b2);
    combine_kernel<<<(NTOK * DDIM / 4) / 256, 256>>>(out);
}

// round 7
// speedup vs baseline: 1.5154x; 1.5154x over previous
#include <cuda_runtime.h>
#include <stdint.h>

#define NTOK 16384
#define DDIM 512
#define HDIM 2048
#define NEXP 8
#define NPAIR (NTOK * 2)

// ---------------- device scratch (allocation-free) ----------------
__device__ int g_count[NEXP];
__device__ int g_base[NEXP];
__device__ int g_i64;
__device__ int g_list[NEXP * NTOK];            // entries: token*2 + slot
__device__ unsigned char g_v1[NTOK];
__device__ float g_xc[(size_t)NTOK * DDIM];    // tf32-rounded x
__device__ float g_W1t[(size_t)NEXP * DDIM * HDIM];  // [E][H][D] K-major
__device__ float g_W2t[(size_t)NEXP * DDIM * HDIM];  // [E][D][H] K-major
__device__ float g_h[((size_t)NPAIR + 128) * HDIM];  // compacted hidden
__device__ float g_y[(size_t)NPAIR * DDIM];

// ---------------- helpers ----------------
__device__ __forceinline__ uint32_t smem_to_u32(const void* p) {
    uint32_t a;
    asm("{ .reg .u64 t; cvta.to.shared.u64 t, %1; cvt.u32.u64 %0, t; }"
        : "=r"(a) : "l"(p));
    return a;
}
__device__ __forceinline__ float totf32(float f) {
    uint32_t u;
    asm("cvt.rna.tf32.f32 %0, %1;" : "=r"(u) : "f"(f));
    return __uint_as_float(u);
}
#define CP_ASYNC16(saddr, gptr) \
    asm volatile("cp.async.cg.shared.global [%0], [%1], 16;" :: "r"(saddr), "l"(gptr))
#define CP_COMMIT() asm volatile("cp.async.commit_group;" ::: "memory")
#define CP_WAIT1() asm volatile("cp.async.wait_group 1;" ::: "memory")

__device__ __forceinline__ void mma_tf32(float* c, const uint32_t* a, const uint32_t* b) {
    asm volatile(
        "mma.sync.aligned.m16n8k8.row.col.f32.tf32.tf32.f32 "
        "{%0,%1,%2,%3}, {%4,%5,%6,%7}, {%8,%9}, {%0,%1,%2,%3};"
        : "+f"(c[0]), "+f"(c[1]), "+f"(c[2]), "+f"(c[3])
        : "r"(a[0]), "r"(a[1]), "r"(a[2]), "r"(a[3]), "r"(b[0]), "r"(b[1]));
}
#define LDSM_X4(r0, r1, r2, r3, addr) \
    asm volatile("ldmatrix.sync.aligned.x4.m8n8.shared.b16 {%0,%1,%2,%3}, [%4];" \
                 : "=r"(r0), "=r"(r1), "=r"(r2), "=r"(r3) : "r"(addr))

// ---------------- routing ----------------
__global__ void prep_kernel(const int* __restrict__ aw) {
    __shared__ int nz;
    if (threadIdx.x == 0) nz = 0;
    __syncthreads();
    if (threadIdx.x < 64)
        if (aw[2 * threadIdx.x + 1] != 0) atomicOr(&nz, 1);
    __syncthreads();
    if (threadIdx.x < NEXP) g_count[threadIdx.x] = 0;
    if (threadIdx.x == 0) g_i64 = (nz == 0) ? 1 : 0;
}

__global__ void route_kernel(const int* __restrict__ aw) {
    int t = blockIdx.x * blockDim.x + threadIdx.x;
    if (t >= NTOK) return;
    int e0, e1;
    if (g_i64) { e0 = aw[4 * t]; e1 = aw[4 * t + 2]; }
    else       { e0 = aw[2 * t]; e1 = aw[2 * t + 1]; }
    int p = atomicAdd(&g_count[e0], 1);
    g_list[e0 * NTOK + p] = 2 * t;
    int v1 = (e1 != e0) ? 1 : 0;
    g_v1[t] = (unsigned char)v1;
    if (v1) {
        p = atomicAdd(&g_count[e1], 1);
        g_list[e1 * NTOK + p] = 2 * t + 1;
    }
}

__global__ void base_kernel() {
    if (threadIdx.x == 0) {
        int s = 0;
        for (int e = 0; e < NEXP; e++) { g_base[e] = s; s += g_count[e]; }
    }
}

// ---------------- input rounding / weight transpose ----------------
__global__ void xconv_kernel(const float* __restrict__ x) {
    size_t i = (size_t)blockIdx.x * blockDim.x + threadIdx.x;
    float4 v = ((const float4*)x)[i];
    v.x = totf32(v.x); v.y = totf32(v.y); v.z = totf32(v.z); v.w = totf32(v.w);
    ((float4*)g_xc)[i] = v;
}

// in: [E][R][C] -> out: [E][C][R], tf32-rounded
__global__ void transpose_kernel(const float* __restrict__ in, int R, int C, int which) {
    __shared__ float t[32][33];
    float* out = which ? g_W2t : g_W1t;
    int e = blockIdx.z;
    const float* I = in + (size_t)e * R * C;
    float* O = out + (size_t)e * R * C;
    int c0 = blockIdx.x * 32, r0 = blockIdx.y * 32;
    int tx = threadIdx.x, ty = threadIdx.y;
#pragma unroll
    for (int j = 0; j < 32; j += 8)
        t[ty + j][tx] = totf32(I[(size_t)(r0 + ty + j) * C + c0 + tx]);
    __syncthreads();
#pragma unroll
    for (int j = 0; j < 32; j += 8)
        O[(size_t)(c0 + ty + j) * R + r0 + tx] = t[tx][ty + j];
}

// ---------------- tf32 mma.sync gather-GEMM ----------------
// CTA tile 128x128, BK=32, 3-stage cp.async ring, ldmatrix fragment loads,
// ONE __syncthreads per K-stage, 2 CTAs/SM.
// Exactly ONE commit_group per iteration so wait_group counting is invariant
// (tail iterations commit an EMPTY group — removing that caused the R6 race).
#define ASTRIDE 36
#define ABUF (128 * ASTRIDE)            // floats per stage per operand
#define ABUFBYTES (ABUF * 4)            // 18432
#define NSTG 3
#define SMEM_BYTES (2 * NSTG * ABUFBYTES)   // 110592

// MODE 1: h = relu(xc @ W1t^T + b1)  KD=512,  ND=2048, out rows compact
// MODE 2: y = h @ W2t^T + b2         KD=2048, ND=512,  out rows scattered by list
template <int MODE>
__global__ __launch_bounds__(256, 2) void moe_mma(const float* __restrict__ biasAll) {
    constexpr int KD = (MODE == 1) ? DDIM : HDIM;
    constexpr int ND = (MODE == 1) ? HDIM : DDIM;
    constexpr int NS = KD / 32;

    const int e = blockIdx.z;
    const int count = g_count[e];
    const int m0 = blockIdx.y * 128;
    if (m0 >= count) return;
    const int n0 = blockIdx.x * 128;
    const int baseE = g_base[e];
    const float* __restrict__ W = (MODE == 1 ? g_W1t : g_W2t) + (size_t)e * KD * ND;
    const float* __restrict__ bias = biasAll + e * ND;
    const int* __restrict__ list = g_list + e * NTOK;

    extern __shared__ float smf[];
    const uint32_t sbase = smem_to_u32(smf);

    const int tid = threadIdx.x;
    const int wid = tid >> 5, lid = tid & 31;
    const int wm = wid >> 2, wn = wid & 3;         // warp grid 2(M) x 4(N)
    const int g = lid >> 2, tg = lid & 3;

    // ---- cp.async mapping: 8 x 16B chunks per thread per stage
    const int rA = tid >> 3;       // base row 0..31
    const int c16 = tid & 7;       // 16B chunk within 128B row
    const float* asrc[4];
    const float* bsrc[4];
    uint32_t aoff[4], boff[4];
#pragma unroll
    for (int j = 0; j < 4; j++) {
        int r = rA + 32 * j;
        int gm = m0 + r;
        if (gm >= count) gm = count - 1;
        const float* Ar;
        if (MODE == 1) Ar = g_xc + (size_t)(list[gm] >> 1) * DDIM;
        else           Ar = g_h + (size_t)(baseE + gm) * HDIM;
        asrc[j] = Ar + c16 * 4;
        aoff[j] = sbase + (uint32_t)(r * ASTRIDE + c16 * 4) * 4;
        bsrc[j] = W + (size_t)(n0 + r) * KD + c16 * 4;
        boff[j] = sbase + (uint32_t)(NSTG * ABUF + r * ASTRIDE + c16 * 4) * 4;
    }

    // ---- ldmatrix per-thread addresses (byte offsets within a stage buffer)
    uint32_t lma[4];
#pragma unroll
    for (int i = 0; i < 4; i++) {
        int row = wm * 64 + i * 16 + ((lid >> 3) & 1) * 8 + (lid & 7);
        lma[i] = (uint32_t)(row * ASTRIDE + ((lid >> 4) & 1) * 4) * 4;
    }
    uint32_t lmb[2];
#pragma unroll
    for (int p = 0; p < 2; p++) {
        int row = wn * 32 + (p * 2 + ((lid >> 4) & 1)) * 8 + (lid & 7);
        lmb[p] = (uint32_t)(row * ASTRIDE + ((lid >> 3) & 1) * 4) * 4;
    }

    float acc[4][4][4];
#pragma unroll
    for (int i = 0; i < 4; i++)
#pragma unroll
        for (int j = 0; j < 4; j++)
#pragma unroll
            for (int q = 0; q < 4; q++) acc[i][j][q] = 0.f;

    auto load_stage = [&](int s) {
        const uint32_t bufo = (uint32_t)(s % NSTG) * ABUFBYTES;
        const int k0 = s * 32;
#pragma unroll
        for (int j = 0; j < 4; j++) {
            CP_ASYNC16(aoff[j] + bufo, asrc[j] + k0);
            CP_ASYNC16(boff[j] + bufo, bsrc[j] + k0);
        }
        CP_COMMIT();
    };

    load_stage(0);
    load_stage(1);

    for (int s = 0; s < NS; s++) {
        CP_WAIT1();          // pending = {s, s+1}; retires group s -> stage s resident
        __syncthreads();     // all threads past wait; stage s-1 readers done
        if (s + 2 < NS) load_stage(s + 2);  // writes buffer (s-1)%3
        else CP_COMMIT();                    // EMPTY group: keeps wait counting invariant

        const uint32_t sa = sbase + (uint32_t)(s % NSTG) * ABUFBYTES;
        const uint32_t sb = sa + (uint32_t)NSTG * ABUFBYTES;
#pragma unroll
        for (int ks = 0; ks < 4; ks++) {
            const uint32_t kb = (uint32_t)ks * 32;  // 8 floats
            uint32_t a[4][4], b[2][4];
#pragma unroll
            for (int i = 0; i < 4; i++)
                LDSM_X4(a[i][0], a[i][1], a[i][2], a[i][3], sa + lma[i] + kb);
#pragma unroll
            for (int p = 0; p < 2; p++)
                LDSM_X4(b[p][0], b[p][1], b[p][2], b[p][3], sb + lmb[p] + kb);
#pragma unroll
            for (int i = 0; i < 4; i++)
#pragma unroll
                for (int j = 0; j < 4; j++)
                    mma_tf32(acc[i][j], a[i], &b[j >> 1][(j & 1) * 2]);
        }
    }

    // ---- epilogue: bias (+relu(+tf32 re-round)), scatter per mma row layout
#pragma unroll
    for (int i = 0; i < 4; i++) {
#pragma unroll
        for (int half = 0; half < 2; half++) {
            int gm = m0 + wm * 64 + i * 16 + half * 8 + g;
            if (gm >= count) continue;
            float* orow;
            if (MODE == 1) orow = g_h + (size_t)(baseE + gm) * HDIM + n0;
            else           { int ent = list[gm]; orow = g_y + (size_t)ent * DDIM + n0; }
#pragma unroll
            for (int j = 0; j < 4; j++) {
                int col = wn * 32 + j * 8 + tg * 2;
                float2 bv = *(const float2*)(bias + n0 + col);
                float v0 = acc[i][j][2 * half + 0] + bv.x;
                float v1 = acc[i][j][2 * half + 1] + bv.y;
                if (MODE == 1) {
                    v0 = totf32(fmaxf(v0, 0.f));
                    v1 = totf32(fmaxf(v1, 0.f));
                }
                *(float2*)(orow + col) = make_float2(v0, v1);
            }
        }
    }
}

// ---------------- combine ----------------
__global__ void combine_kernel(float* __restrict__ out) {
    int idx = blockIdx.x * blockDim.x + threadIdx.x;
    if (idx >= NTOK * DDIM / 4) return;
    int t = idx / (DDIM / 4);
    int d4 = idx % (DDIM / 4);
    float4 v = ((const float4*)(g_y + (size_t)(2 * t) * DDIM))[d4];
    if (g_v1[t]) {
        float4 w = ((const float4*)(g_y + (size_t)(2 * t + 1) * DDIM))[d4];
        v.x += w.x; v.y += w.y; v.z += w.z; v.w += w.w;
    }
    v.x *= 0.5f; v.y *= 0.5f; v.z *= 0.5f; v.w *= 0.5f;
    ((float4*)out)[idx] = v;
}

// ---------------- launch ----------------
extern "C" void kernel_launch(void* const* d_in, const int* in_sizes, int n_in,
                              void* d_out, int out_size) {
    const float* x  = (const float*)d_in[0];
    const int*   aw = (const int*)d_in[1];
    const float* W1 = (const float*)d_in[2];
    const float* b1 = (const float*)d_in[3];
    const float* W2 = (const float*)d_in[4];
    const float* b2 = (const float*)d_in[5];
    float* out = (float*)d_out;

    cudaFuncSetAttribute(moe_mma<1>, cudaFuncAttributeMaxDynamicSharedMemorySize, SMEM_BYTES);
    cudaFuncSetAttribute(moe_mma<2>, cudaFuncAttributeMaxDynamicSharedMemorySize, SMEM_BYTES);

    prep_kernel<<<1, 256>>>(aw);
    route_kernel<<<NTOK / 256, 256>>>(aw);
    base_kernel<<<1, 32>>>();
    xconv_kernel<<<(NTOK * DDIM / 4) / 256, 256>>>(x);
    transpose_kernel<<<dim3(HDIM / 32, DDIM / 32, NEXP), dim3(32, 8)>>>(W1, DDIM, HDIM, 0);
    transpose_kernel<<<dim3(DDIM / 32, HDIM / 32, NEXP), dim3(32, 8)>>>(W2, HDIM, DDIM, 1);
    moe_mma<1><<<dim3(HDIM / 128, NTOK / 128, NEXP), 256, SMEM_BYTES>>>(b1);
    moe_mma<2><<<dim3(DDIM / 128, NTOK / 128, NEXP), 256, SMEM_BYTES>>>(b2);
    combine_kernel<<<(NTOK * DDIM / 4) / 256, 256>>>(out);
}